// round 16
// baseline (speedup 1.0000x reference)
#include <cuda_runtime.h>
#include <cuda_bf16.h>
#include <cstdint>

// Problem constants
#define TT 512
#define BB 64
#define II 256
#define HH 1024
#define OO 256
#define OUT_ELEMS   (TT * BB * OO)

// ---------------- recurrent kernel configuration (HMMA mma.sync path) ------
#define REC_CTAS    128           // 4 b-quarters x 32 j-slices
#define REC_THREADS 256

// smem word layout (uint32 words): wt [2][32][516] + red [8][16][36]
#define WT_WORDS    (2 * 32 * 516)        // 33024 words = 132096 B
#define RED_WORDS   (8 * 16 * 36)         //  4608 words =  18432 B
#define SM_WT       0
#define SM_RED      WT_WORDS
#define REC_SMEM_BYTES ((WT_WORDS + RED_WORDS) * 4)   // 150528

// ---------------- split-bf16 HMMA GEMM configuration -----------------------
#define GEMM_SMEM_WORDS (2 * 9216)        // sA 9216 + sB 9216 words
#define GEMM_SMEM_BYTES (GEMM_SMEM_WORDS * 4)   // 73728

// Scratch (device globals: no cudaMalloc allowed)
__device__ float g_pre[TT * BB * HH];
__device__ __align__(16) __nv_bfloat16 g_xh[TT * BB * II];
__device__ __align__(16) __nv_bfloat16 g_xl[TT * BB * II];
__device__ __align__(16) __nv_bfloat16 g_wih[HH * II];
__device__ __align__(16) __nv_bfloat16 g_wil[HH * II];
__device__ __align__(16) __nv_bfloat16 g_woh[OO * HH];
__device__ __align__(16) __nv_bfloat16 g_wol[OO * HH];
__device__ __align__(16) __nv_bfloat16 g_hhh[(TT + 1) * BB * HH];  // h history hi
__device__ __align__(16) __nv_bfloat16 g_hhl[(TT + 1) * BB * HH];  // h history lo
__device__ unsigned g_arrived = 0;
__device__ unsigned g_flags[REC_CTAS][32];    // one 128B line per CTA

__device__ __forceinline__ void grid_sync() {
    __syncthreads();
    if (threadIdx.x == 0) {
        __threadfence();
        unsigned ticket = atomicAdd(&g_arrived, 1u) + 1u;
        unsigned target = ((ticket + (REC_CTAS - 1u)) / REC_CTAS) * REC_CTAS;
        unsigned cur;
        do {
            asm volatile("ld.acquire.gpu.global.u32 %0, [%1];"
                         : "=r"(cur) : "l"(&g_arrived) : "memory");
        } while ((int)(cur - target) < 0);
        __threadfence();
    }
    __syncthreads();
}

__device__ __forceinline__ void mma16816(float* d, uint32_t a0, uint32_t a1,
                                         uint32_t a2, uint32_t a3,
                                         uint32_t b0, uint32_t b1) {
    asm volatile(
        "mma.sync.aligned.m16n8k16.row.col.f32.bf16.bf16.f32 "
        "{%0,%1,%2,%3}, {%4,%5,%6,%7}, {%8,%9}, {%0,%1,%2,%3};"
        : "+f"(d[0]), "+f"(d[1]), "+f"(d[2]), "+f"(d[3])
        : "r"(a0), "r"(a1), "r"(a2), "r"(a3), "r"(b0), "r"(b1));
}

__device__ __forceinline__ uint32_t ldg_cg(const uint32_t* p) {
    uint32_t v;
    asm volatile("ld.global.cg.u32 %0, [%1];" : "=r"(v) : "l"(p));
    return v;
}

// ---------------------------------------------------------------------------
// fp32 -> bf16 hi/lo split (vectorized by 4)
// ---------------------------------------------------------------------------
__global__ void __launch_bounds__(256) split_kernel(
    const float* __restrict__ src, __nv_bfloat16* __restrict__ hi,
    __nv_bfloat16* __restrict__ lo, int n4)
{
    int i = blockIdx.x * 256 + threadIdx.x;
    if (i >= n4) return;
    float4 v = ((const float4*)src)[i];
    __nv_bfloat16 h[4], l[4];
    float vv[4] = {v.x, v.y, v.z, v.w};
    #pragma unroll
    for (int j = 0; j < 4; j++) {
        h[j] = __float2bfloat16(vv[j]);
        l[j] = __float2bfloat16(vv[j] - __bfloat162float(h[j]));
    }
    ((uint2*)hi)[i] = *(uint2*)h;
    ((uint2*)lo)[i] = *(uint2*)l;
}

// ---------------------------------------------------------------------------
// Split-bf16 HMMA GEMM (unchanged; measured 177us on big shape, tensor=48%)
// ---------------------------------------------------------------------------
__global__ void __launch_bounds__(256) gemm_mma_split(
    const __nv_bfloat16* __restrict__ Ah, const __nv_bfloat16* __restrict__ Al,
    const __nv_bfloat16* __restrict__ Bh, const __nv_bfloat16* __restrict__ Bl,
    const float* __restrict__ bias, float* __restrict__ C,
    int M, int N, int K)
{
    extern __shared__ __align__(16) uint32_t sm[];
    uint32_t* sA = sm;                 // [2 buf][2 mat][64 row][36 w]
    uint32_t* sB = sm + 9216;          // same

    const int tid   = threadIdx.x;
    const int wid   = tid >> 5;
    const int lane  = tid & 31;
    const int mBase = blockIdx.x * 64;
    const int nBase = blockIdx.y * 64;
    const int wm    = wid >> 2;
    const int wn    = wid & 3;
    const int lg    = lane >> 2;
    const int lc    = lane & 3;

    const uint32_t sA_sm = (uint32_t)__cvta_generic_to_shared(sA);
    const uint32_t sB_sm = (uint32_t)__cvta_generic_to_shared(sB);

    auto stage = [&](int c, int buf) {
        #pragma unroll
        for (int i = 0; i < 4; i++) {
            int L   = tid + i * 256;
            int mat = L >> 9;
            int rem = L & 511;
            int row = rem >> 3;
            int seg = rem & 7;
            const __nv_bfloat16* srcA =
                (mat ? Al : Ah) + (size_t)(mBase + row) * K + c * 64 + seg * 8;
            uint32_t dstA = sA_sm +
                (((buf * 2 + mat) * 64 + row) * 36 + seg * 4) * 4;
            asm volatile("cp.async.cg.shared.global [%0], [%1], 16;"
                         :: "r"(dstA), "l"(srcA));
            const __nv_bfloat16* srcB =
                (mat ? Bl : Bh) + (size_t)(nBase + row) * K + c * 64 + seg * 8;
            uint32_t dstB = sB_sm +
                (((buf * 2 + mat) * 64 + row) * 36 + seg * 4) * 4;
            asm volatile("cp.async.cg.shared.global [%0], [%1], 16;"
                         :: "r"(dstB), "l"(srcB));
        }
        asm volatile("cp.async.commit_group;");
    };

    float acc[2][2][4] = {};
    const int NC = K >> 6;

    stage(0, 0);

    for (int c = 0; c < NC; c++) {
        const int buf = c & 1;
        if (c + 1 < NC) {
            stage(c + 1, buf ^ 1);
            asm volatile("cp.async.wait_group 1;");
        } else {
            asm volatile("cp.async.wait_group 0;");
        }
        __syncthreads();

        const uint32_t* aH = sA + (buf * 2 + 0) * 2304;
        const uint32_t* aL = sA + (buf * 2 + 1) * 2304;
        const uint32_t* bH = sB + (buf * 2 + 0) * 2304;
        const uint32_t* bL = sB + (buf * 2 + 1) * 2304;

        #pragma unroll
        for (int s = 0; s < 4; s++) {
            const int w = s * 8 + lc;
            uint32_t ah[2][4], al[2][4], bh[2][2], bl[2][2];
            #pragma unroll
            for (int mt = 0; mt < 2; mt++) {
                const int r = wm * 32 + mt * 16 + lg;
                ah[mt][0] = aH[r * 36 + w];
                ah[mt][1] = aH[(r + 8) * 36 + w];
                ah[mt][2] = aH[r * 36 + w + 4];
                ah[mt][3] = aH[(r + 8) * 36 + w + 4];
                al[mt][0] = aL[r * 36 + w];
                al[mt][1] = aL[(r + 8) * 36 + w];
                al[mt][2] = aL[r * 36 + w + 4];
                al[mt][3] = aL[(r + 8) * 36 + w + 4];
            }
            #pragma unroll
            for (int nt = 0; nt < 2; nt++) {
                const int r = wn * 16 + nt * 8 + lg;
                bh[nt][0] = bH[r * 36 + w];
                bh[nt][1] = bH[r * 36 + w + 4];
                bl[nt][0] = bL[r * 36 + w];
                bl[nt][1] = bL[r * 36 + w + 4];
            }
            #pragma unroll
            for (int mt = 0; mt < 2; mt++)
                #pragma unroll
                for (int nt = 0; nt < 2; nt++) {
                    mma16816(acc[mt][nt], ah[mt][0], ah[mt][1], ah[mt][2],
                             ah[mt][3], bh[nt][0], bh[nt][1]);
                    mma16816(acc[mt][nt], ah[mt][0], ah[mt][1], ah[mt][2],
                             ah[mt][3], bl[nt][0], bl[nt][1]);
                    mma16816(acc[mt][nt], al[mt][0], al[mt][1], al[mt][2],
                             al[mt][3], bh[nt][0], bh[nt][1]);
                }
        }
        __syncthreads();
    }

    #pragma unroll
    for (int mt = 0; mt < 2; mt++) {
        #pragma unroll
        for (int nt = 0; nt < 2; nt++) {
            const int row = mBase + wm * 32 + mt * 16 + lg;
            const int col = nBase + wn * 16 + nt * 8 + lc * 2;
            const float b0 = __ldg(bias + col);
            const float b1 = __ldg(bias + col + 1);
            float* d = acc[mt][nt];
            *(float2*)&C[(size_t)row * N + col] =
                make_float2(d[0] + b0, d[1] + b1);
            *(float2*)&C[(size_t)(row + 8) * N + col] =
                make_float2(d[2] + b0, d[3] + b1);
        }
    }
}

// ---------------------------------------------------------------------------
// HMMA persistent recurrence, direct-LDG version.
// 128 CTAs: bq = bx>>5 (16 b-rows), jt = bx&31 (32 j-cols). 8 warps = 8-way
// k-split (warp kq: k in [g*512+kq*64,+64) per half g).
// A fragments load straight from the bf16 h history via ld.global.cg (L2-only;
// same coherence as the old cp.async.cg path) -- no smem staging at all.
// B (wR slice) resident in smem. Epilogue publishes the bf16 exchange, fences,
// releases, and only then stores the fp32 hid output.
// ---------------------------------------------------------------------------
__global__ void __launch_bounds__(REC_THREADS, 1) rnn_rec_mma(
    const float* __restrict__ pre,
    const float* __restrict__ h0,
    const float* __restrict__ wR,
    float* __restrict__ hid)
{
    extern __shared__ __align__(16) uint32_t smw[];
    uint32_t* wt  = smw + SM_WT;                  // [2][32][516]
    float*    red = reinterpret_cast<float*>(smw + SM_RED);  // [8][16][36]

    const int tid   = threadIdx.x;
    const int wid   = tid >> 5;
    const int lane  = tid & 31;
    const int bx    = blockIdx.x;
    const int jt    = bx & 31;
    const int bq    = bx >> 5;
    const int jbase = jt * 32;
    const int bBase = bq * 16;

    // ---- Stage wR slice as bf16 hi/lo, layout [mat][n][k] ----
    {
        __nv_bfloat16* wb = reinterpret_cast<__nv_bfloat16*>(wt);
        for (int idx = tid; idx < 32 * HH; idx += REC_THREADS) {
            int n = idx & 31, k = idx >> 5;
            float v = wR[k * HH + jbase + n];
            __nv_bfloat16 hi = __float2bfloat16(v);
            __nv_bfloat16 lo = __float2bfloat16(v - __bfloat162float(hi));
            wb[(size_t)n * 1032 + k]        = hi;   // mat 0
            wb[(size_t)(32 + n) * 1032 + k] = lo;   // mat 1
        }
    }
    // ---- h0 -> history slot 0 (CTA 0 only) ----
    if (bx == 0) {
        for (int idx = tid; idx < BB * HH; idx += REC_THREADS) {
            float v = h0[idx & (HH - 1)];
            __nv_bfloat16 hi = __float2bfloat16(v);
            __nv_bfloat16 lo = __float2bfloat16(v - __bfloat162float(hi));
            g_hhh[idx] = hi;
            g_hhl[idx] = lo;
        }
    }
    if (tid == 0) g_flags[bx][0] = 0u;   // reset for graph replays
    grid_sync();

    const int kq = wid;                  // 0..7 k-split
    const int lg = lane >> 2;            // 0..7
    const int lc = lane & 3;             // 0..3

    const int ebl = tid >> 4;            // 0..15
    const int ejl = (tid & 15) * 2;      // 0,2,..,30
    const int eb  = bBase + ebl;

    unsigned* myFlag = &g_flags[bx][0];

    // This warp's 4 producer flags (2 per half).
    const unsigned* fA0 = &g_flags[bq * 32 + 2 * kq][0];
    const unsigned* fA1 = &g_flags[bq * 32 + 2 * kq + 1][0];
    const unsigned* fB0 = &g_flags[bq * 32 + 16 + 2 * kq][0];
    const unsigned* fB1 = &g_flags[bq * 32 + 16 + 2 * kq + 1][0];

    const uint32_t* wth = wt;
    const uint32_t* wtl = wt + 32 * 516;

    for (int t = 0; t < TT; t++) {
        // Prefetch pre for this thread's outputs.
        const float* preRow = pre + ((size_t)t * BB + eb) * HH + jbase + ejl;
        float2 pv = __ldg((const float2*)preRow);

        // h rows as uint32 words: row stride = HH/2 = 512 words.
        const uint32_t* Hh = (const uint32_t*)(g_hhh + (size_t)t * (BB * HH)
                                               + (size_t)bBase * HH);
        const uint32_t* Hl = (const uint32_t*)(g_hhl + (size_t)t * (BB * HH)
                                               + (size_t)bBase * HH);

        float d[4][4] = {};

        #pragma unroll
        for (int g = 0; g < 2; g++) {
            // Wait for this half's 2 producers (all lanes acquire-poll).
            if (t > 0) {
                const unsigned* f0 = g ? fB0 : fA0;
                const unsigned* f1 = g ? fB1 : fA1;
                unsigned c0, c1;
                do {
                    asm volatile("ld.acquire.gpu.global.u32 %0, [%1];"
                                 : "=r"(c0) : "l"(f0) : "memory");
                    asm volatile("ld.acquire.gpu.global.u32 %0, [%1];"
                                 : "=r"(c1) : "l"(f1) : "memory");
                } while ((int)c0 < t || (int)c1 < t);
            }

            #pragma unroll
            for (int s = 0; s < 4; s++) {
                const int w = g * 256 + kq * 32 + s * 8 + lc;

                // A fragments direct from global (L2) -- hi and lo.
                uint32_t a0h = ldg_cg(Hh + lg * 512 + w);
                uint32_t a1h = ldg_cg(Hh + (lg + 8) * 512 + w);
                uint32_t a2h = ldg_cg(Hh + lg * 512 + w + 4);
                uint32_t a3h = ldg_cg(Hh + (lg + 8) * 512 + w + 4);
                uint32_t a0l = ldg_cg(Hl + lg * 512 + w);
                uint32_t a1l = ldg_cg(Hl + (lg + 8) * 512 + w);
                uint32_t a2l = ldg_cg(Hl + lg * 512 + w + 4);
                uint32_t a3l = ldg_cg(Hl + (lg + 8) * 512 + w + 4);

                #pragma unroll
                for (int nt = 0; nt < 4; nt++) {
                    const int nr = nt * 8 + lg;
                    uint32_t b0h = wth[nr * 516 + w];
                    uint32_t b1h = wth[nr * 516 + w + 4];
                    uint32_t b0l = wtl[nr * 516 + w];
                    uint32_t b1l = wtl[nr * 516 + w + 4];
                    mma16816(d[nt], a0h, a1h, a2h, a3h, b0h, b1h);
                    mma16816(d[nt], a0h, a1h, a2h, a3h, b0l, b1l);
                    mma16816(d[nt], a0l, a1l, a2l, a3l, b0h, b1h);
                }
            }
        }

        // ---- write k-split partials to red ----
        {
            float* rp = red + wid * 576;
            #pragma unroll
            for (int nt = 0; nt < 4; nt++) {
                int col = nt * 8 + lc * 2;
                *(float2*)&rp[lg * 36 + col]       = make_float2(d[nt][0], d[nt][1]);
                *(float2*)&rp[(lg + 8) * 36 + col] = make_float2(d[nt][2], d[nt][3]);
            }
        }
        __syncthreads();

        // ---- epilogue: reduce, tanh, publish exchange FIRST, then release,
        //      then the fp32 output stores (off the inter-CTA critical path).
        float v0, v1;
        {
            float s0 = 0.f, s1 = 0.f;
            #pragma unroll
            for (int q = 0; q < 8; q++) {
                float2 p = *(float2*)&red[q * 576 + ebl * 36 + ejl];
                s0 += p.x; s1 += p.y;
            }
            v0 = tanhf(pv.x + s0);
            v1 = tanhf(pv.y + s1);

            __nv_bfloat16* nxh = g_hhh + (size_t)(t + 1) * (BB * HH);
            __nv_bfloat16* nxl = g_hhl + (size_t)(t + 1) * (BB * HH);
            __nv_bfloat16 h2[2], l2[2];
            h2[0] = __float2bfloat16(v0);
            h2[1] = __float2bfloat16(v1);
            l2[0] = __float2bfloat16(v0 - __bfloat162float(h2[0]));
            l2[1] = __float2bfloat16(v1 - __bfloat162float(h2[1]));
            *(uint32_t*)&nxh[(size_t)eb * HH + jbase + ejl] = *(uint32_t*)h2;
            *(uint32_t*)&nxl[(size_t)eb * HH + jbase + ejl] = *(uint32_t*)l2;
        }

        __threadfence();
        __syncthreads();
        if (tid == 0) {
            unsigned v = (unsigned)(t + 1);
            asm volatile("st.release.gpu.global.u32 [%0], %1;"
                         :: "l"(myFlag), "r"(v) : "memory");
        }

        // fp32 output store (consumers never read this; after release).
        float* hNew = hid + (size_t)t * (BB * HH);
        *(float2*)&hNew[(size_t)eb * HH + jbase + ejl] = make_float2(v0, v1);
    }
}

// ---------------------------------------------------------------------------
// Launch: splits -> HMMA pre-GEMM -> persistent HMMA recurrence -> HMMA
// out-GEMM (out-GEMM reads the recurrent kernel's bf16 h history directly).
// ---------------------------------------------------------------------------
extern "C" void kernel_launch(void* const* d_in, const int* in_sizes, int n_in,
                              void* d_out, int out_size)
{
    const float* x  = (const float*)d_in[0];
    const float* h0 = (const float*)d_in[1];
    const float* wI = (const float*)d_in[2];
    const float* wR = (const float*)d_in[3];
    const float* wO = (const float*)d_in[4];
    const float* bR = (const float*)d_in[5];
    const float* bO = (const float*)d_in[6];

    float* outp = (float*)d_out;            // [T,B,O]
    float* hid  = outp + OUT_ELEMS;         // [T,B,H]

    float* pre = nullptr;
    cudaGetSymbolAddress((void**)&pre, g_pre);
    __nv_bfloat16 *xh, *xl, *wih, *wil, *woh, *wol, *hhh, *hhl;
    cudaGetSymbolAddress((void**)&xh,  g_xh);
    cudaGetSymbolAddress((void**)&xl,  g_xl);
    cudaGetSymbolAddress((void**)&wih, g_wih);
    cudaGetSymbolAddress((void**)&wil, g_wil);
    cudaGetSymbolAddress((void**)&woh, g_woh);
    cudaGetSymbolAddress((void**)&wol, g_wol);
    cudaGetSymbolAddress((void**)&hhh, g_hhh);
    cudaGetSymbolAddress((void**)&hhl, g_hhl);

    cudaFuncSetAttribute(rnn_rec_mma,
                         cudaFuncAttributeMaxDynamicSharedMemorySize,
                         REC_SMEM_BYTES);
    cudaFuncSetAttribute(gemm_mma_split,
                         cudaFuncAttributeMaxDynamicSharedMemorySize,
                         GEMM_SMEM_BYTES);

    // fp32 -> bf16 hi/lo splits
    split_kernel<<<(TT * BB * II / 4 + 255) / 256, 256>>>(x, xh, xl, TT * BB * II / 4);
    split_kernel<<<(HH * II / 4 + 255) / 256, 256>>>(wI, wih, wil, HH * II / 4);
    split_kernel<<<(OO * HH / 4 + 255) / 256, 256>>>(wO, woh, wol, OO * HH / 4);

    // pre[T*B, H] = x @ wI^T + bR   (HMMA split)
    gemm_mma_split<<<dim3(TT * BB / 64, HH / 64), 256, GEMM_SMEM_BYTES>>>(
        xh, xl, wih, wil, bR, pre, TT * BB, HH, II);

    // recurrence (writes hid fp32 + bf16 hi/lo history)
    rnn_rec_mma<<<REC_CTAS, REC_THREADS, REC_SMEM_BYTES>>>(pre, h0, wR, hid);

    // outputs[T*B, O] = hid @ wO^T + bO  (HMMA split, A = bf16 history slot 1+)
    gemm_mma_split<<<dim3(TT * BB / 64, OO / 64), 256, GEMM_SMEM_BYTES>>>(
        hhh + BB * HH, hhl + BB * HH, woh, wol, bO, outp, TT * BB, OO, HH);
}

// round 17
// speedup vs baseline: 1.3481x; 1.3481x over previous
#include <cuda_runtime.h>
#include <cuda_bf16.h>
#include <cstdint>

// Problem constants
#define TT 512
#define BB 64
#define II 256
#define HH 1024
#define OO 256
#define OUT_ELEMS   (TT * BB * OO)

// ---------------- recurrent kernel configuration (HMMA mma.sync path) ------
#define REC_CTAS    128           // 4 b-quarters x 32 j-slices
#define REC_THREADS 512           // 16 warps = 16-way k-split

// smem word layout (uint32 words)
#define WT_WORDS    (2 * 32 * 516)        // 33024 words = 132096 B
#define HB_WORDS    (2 * 16 * 516)        // 16512 words =  66048 B
#define RED_WORDS   (8 * 16 * 36)         //  4608 words =  18432 B
#define SM_WT       0
#define SM_HB       WT_WORDS
#define SM_RED      (WT_WORDS + HB_WORDS)
#define REC_SMEM_BYTES ((WT_WORDS + HB_WORDS + RED_WORDS) * 4)   // 216576

// ---------------- split-bf16 HMMA GEMM configuration -----------------------
#define GEMM_SMEM_WORDS (2 * 9216)
#define GEMM_SMEM_BYTES (GEMM_SMEM_WORDS * 4)   // 73728

// Scratch (device globals: no cudaMalloc allowed)
__device__ float g_pre[TT * BB * HH];
__device__ __align__(16) __nv_bfloat16 g_xh[TT * BB * II];
__device__ __align__(16) __nv_bfloat16 g_xl[TT * BB * II];
__device__ __align__(16) __nv_bfloat16 g_wih[HH * II];
__device__ __align__(16) __nv_bfloat16 g_wil[HH * II];
__device__ __align__(16) __nv_bfloat16 g_woh[OO * HH];
__device__ __align__(16) __nv_bfloat16 g_wol[OO * HH];
__device__ __align__(16) __nv_bfloat16 g_hhh[(TT + 1) * BB * HH];  // h history hi
__device__ __align__(16) __nv_bfloat16 g_hhl[(TT + 1) * BB * HH];  // h history lo
__device__ unsigned g_arrived = 0;
__device__ unsigned g_flags[REC_CTAS][32];    // one 128B line per CTA

__device__ __forceinline__ void grid_sync() {
    __syncthreads();
    if (threadIdx.x == 0) {
        __threadfence();
        unsigned ticket = atomicAdd(&g_arrived, 1u) + 1u;
        unsigned target = ((ticket + (REC_CTAS - 1u)) / REC_CTAS) * REC_CTAS;
        unsigned cur;
        do {
            asm volatile("ld.acquire.gpu.global.u32 %0, [%1];"
                         : "=r"(cur) : "l"(&g_arrived) : "memory");
        } while ((int)(cur - target) < 0);
        __threadfence();
    }
    __syncthreads();
}

__device__ __forceinline__ void mma16816(float* d, uint32_t a0, uint32_t a1,
                                         uint32_t a2, uint32_t a3,
                                         uint32_t b0, uint32_t b1) {
    asm volatile(
        "mma.sync.aligned.m16n8k16.row.col.f32.bf16.bf16.f32 "
        "{%0,%1,%2,%3}, {%4,%5,%6,%7}, {%8,%9}, {%0,%1,%2,%3};"
        : "+f"(d[0]), "+f"(d[1]), "+f"(d[2]), "+f"(d[3])
        : "r"(a0), "r"(a1), "r"(a2), "r"(a3), "r"(b0), "r"(b1));
}

// ---------------------------------------------------------------------------
// fp32 -> bf16 hi/lo split (vectorized by 4)
// ---------------------------------------------------------------------------
__global__ void __launch_bounds__(256) split_kernel(
    const float* __restrict__ src, __nv_bfloat16* __restrict__ hi,
    __nv_bfloat16* __restrict__ lo, int n4)
{
    int i = blockIdx.x * 256 + threadIdx.x;
    if (i >= n4) return;
    float4 v = ((const float4*)src)[i];
    __nv_bfloat16 h[4], l[4];
    float vv[4] = {v.x, v.y, v.z, v.w};
    #pragma unroll
    for (int j = 0; j < 4; j++) {
        h[j] = __float2bfloat16(vv[j]);
        l[j] = __float2bfloat16(vv[j] - __bfloat162float(h[j]));
    }
    ((uint2*)hi)[i] = *(uint2*)h;
    ((uint2*)lo)[i] = *(uint2*)l;
}

// ---------------------------------------------------------------------------
// Split-bf16 HMMA GEMM (unchanged; 177us on big shape, tensor=48%)
// ---------------------------------------------------------------------------
__global__ void __launch_bounds__(256) gemm_mma_split(
    const __nv_bfloat16* __restrict__ Ah, const __nv_bfloat16* __restrict__ Al,
    const __nv_bfloat16* __restrict__ Bh, const __nv_bfloat16* __restrict__ Bl,
    const float* __restrict__ bias, float* __restrict__ C,
    int M, int N, int K)
{
    extern __shared__ __align__(16) uint32_t sm[];
    uint32_t* sA = sm;
    uint32_t* sB = sm + 9216;

    const int tid   = threadIdx.x;
    const int wid   = tid >> 5;
    const int lane  = tid & 31;
    const int mBase = blockIdx.x * 64;
    const int nBase = blockIdx.y * 64;
    const int wm    = wid >> 2;
    const int wn    = wid & 3;
    const int lg    = lane >> 2;
    const int lc    = lane & 3;

    const uint32_t sA_sm = (uint32_t)__cvta_generic_to_shared(sA);
    const uint32_t sB_sm = (uint32_t)__cvta_generic_to_shared(sB);

    auto stage = [&](int c, int buf) {
        #pragma unroll
        for (int i = 0; i < 4; i++) {
            int L   = tid + i * 256;
            int mat = L >> 9;
            int rem = L & 511;
            int row = rem >> 3;
            int seg = rem & 7;
            const __nv_bfloat16* srcA =
                (mat ? Al : Ah) + (size_t)(mBase + row) * K + c * 64 + seg * 8;
            uint32_t dstA = sA_sm +
                (((buf * 2 + mat) * 64 + row) * 36 + seg * 4) * 4;
            asm volatile("cp.async.cg.shared.global [%0], [%1], 16;"
                         :: "r"(dstA), "l"(srcA));
            const __nv_bfloat16* srcB =
                (mat ? Bl : Bh) + (size_t)(nBase + row) * K + c * 64 + seg * 8;
            uint32_t dstB = sB_sm +
                (((buf * 2 + mat) * 64 + row) * 36 + seg * 4) * 4;
            asm volatile("cp.async.cg.shared.global [%0], [%1], 16;"
                         :: "r"(dstB), "l"(srcB));
        }
        asm volatile("cp.async.commit_group;");
    };

    float acc[2][2][4] = {};
    const int NC = K >> 6;

    stage(0, 0);

    for (int c = 0; c < NC; c++) {
        const int buf = c & 1;
        if (c + 1 < NC) {
            stage(c + 1, buf ^ 1);
            asm volatile("cp.async.wait_group 1;");
        } else {
            asm volatile("cp.async.wait_group 0;");
        }
        __syncthreads();

        const uint32_t* aH = sA + (buf * 2 + 0) * 2304;
        const uint32_t* aL = sA + (buf * 2 + 1) * 2304;
        const uint32_t* bH = sB + (buf * 2 + 0) * 2304;
        const uint32_t* bL = sB + (buf * 2 + 1) * 2304;

        #pragma unroll
        for (int s = 0; s < 4; s++) {
            const int w = s * 8 + lc;
            uint32_t ah[2][4], al[2][4], bh[2][2], bl[2][2];
            #pragma unroll
            for (int mt = 0; mt < 2; mt++) {
                const int r = wm * 32 + mt * 16 + lg;
                ah[mt][0] = aH[r * 36 + w];
                ah[mt][1] = aH[(r + 8) * 36 + w];
                ah[mt][2] = aH[r * 36 + w + 4];
                ah[mt][3] = aH[(r + 8) * 36 + w + 4];
                al[mt][0] = aL[r * 36 + w];
                al[mt][1] = aL[(r + 8) * 36 + w];
                al[mt][2] = aL[r * 36 + w + 4];
                al[mt][3] = aL[(r + 8) * 36 + w + 4];
            }
            #pragma unroll
            for (int nt = 0; nt < 2; nt++) {
                const int r = wn * 16 + nt * 8 + lg;
                bh[nt][0] = bH[r * 36 + w];
                bh[nt][1] = bH[r * 36 + w + 4];
                bl[nt][0] = bL[r * 36 + w];
                bl[nt][1] = bL[r * 36 + w + 4];
            }
            #pragma unroll
            for (int mt = 0; mt < 2; mt++)
                #pragma unroll
                for (int nt = 0; nt < 2; nt++) {
                    mma16816(acc[mt][nt], ah[mt][0], ah[mt][1], ah[mt][2],
                             ah[mt][3], bh[nt][0], bh[nt][1]);
                    mma16816(acc[mt][nt], ah[mt][0], ah[mt][1], ah[mt][2],
                             ah[mt][3], bl[nt][0], bl[nt][1]);
                    mma16816(acc[mt][nt], al[mt][0], al[mt][1], al[mt][2],
                             al[mt][3], bh[nt][0], bh[nt][1]);
                }
        }
        __syncthreads();
    }

    #pragma unroll
    for (int mt = 0; mt < 2; mt++) {
        #pragma unroll
        for (int nt = 0; nt < 2; nt++) {
            const int row = mBase + wm * 32 + mt * 16 + lg;
            const int col = nBase + wn * 16 + nt * 8 + lc * 2;
            const float b0 = __ldg(bias + col);
            const float b1 = __ldg(bias + col + 1);
            float* d = acc[mt][nt];
            *(float2*)&C[(size_t)row * N + col] =
                make_float2(d[0] + b0, d[1] + b1);
            *(float2*)&C[(size_t)(row + 8) * N + col] =
                make_float2(d[2] + b0, d[3] + b1);
        }
    }
}

// ---------------------------------------------------------------------------
// HMMA persistent recurrence, 512-thread / 16-way k-split version.
// 128 CTAs: bq = bx>>5 (16 b-rows), jt = bx&31 (32 j-cols).
// Warp kq (0..15) covers k in [kq*64, +64) -> exactly 2 producer CTAs
// (jt = 2kq, 2kq+1). Each warp: polls its 2 flags, cp.asyncs its 4KB slice,
// wait_group+syncwarp, 48 HMMA. Cross-warp k-reduce in two phases
// (warps 0-7 write red, warps 8-15 accumulate). 4 warps/SMSP hide latency.
// ---------------------------------------------------------------------------
__global__ void __launch_bounds__(REC_THREADS, 1) rnn_rec_mma(
    const float* __restrict__ pre,
    const float* __restrict__ h0,
    const float* __restrict__ wR,
    float* __restrict__ hid)
{
    extern __shared__ __align__(16) uint32_t smw[];
    uint32_t* wt  = smw + SM_WT;                  // [2][32][516]
    uint32_t* hb  = smw + SM_HB;                  // [2][16][516]
    float*    red = reinterpret_cast<float*>(smw + SM_RED);  // [8][16][36]

    const int tid   = threadIdx.x;
    const int wid   = tid >> 5;
    const int lane  = tid & 31;
    const int bx    = blockIdx.x;
    const int jt    = bx & 31;
    const int bq    = bx >> 5;
    const int jbase = jt * 32;
    const int bBase = bq * 16;

    // ---- Stage wR slice as bf16 hi/lo, layout [mat][n][k] ----
    {
        __nv_bfloat16* wb = reinterpret_cast<__nv_bfloat16*>(wt);
        for (int idx = tid; idx < 32 * HH; idx += REC_THREADS) {
            int n = idx & 31, k = idx >> 5;
            float v = wR[k * HH + jbase + n];
            __nv_bfloat16 hi = __float2bfloat16(v);
            __nv_bfloat16 lo = __float2bfloat16(v - __bfloat162float(hi));
            wb[(size_t)n * 1032 + k]        = hi;   // mat 0
            wb[(size_t)(32 + n) * 1032 + k] = lo;   // mat 1
        }
    }
    // ---- h0 -> history slot 0 (CTA 0 only) ----
    if (bx == 0) {
        for (int idx = tid; idx < BB * HH; idx += REC_THREADS) {
            float v = h0[idx & (HH - 1)];
            __nv_bfloat16 hi = __float2bfloat16(v);
            __nv_bfloat16 lo = __float2bfloat16(v - __bfloat162float(hi));
            g_hhh[idx] = hi;
            g_hhl[idx] = lo;
        }
    }
    if (tid == 0) g_flags[bx][0] = 0u;   // reset for graph replays
    grid_sync();

    const int kq = wid;                  // 0..15 k-split
    const int lg = lane >> 2;            // 0..7
    const int lc = lane & 3;             // 0..3

    // Epilogue constants: 1 output per thread.
    const int ebl = tid >> 5;            // 0..15 local b row
    const int ejl = tid & 31;            // 0..31 local j
    const int eb  = bBase + ebl;

    unsigned* myFlag = &g_flags[bx][0];
    const uint32_t hb_sm = (uint32_t)__cvta_generic_to_shared(hb);

    // This warp's 2 producer flags.
    const unsigned* f0 = &g_flags[bq * 32 + 2 * kq][0];
    const unsigned* f1 = &g_flags[bq * 32 + 2 * kq + 1][0];

    const uint32_t* wth = wt;
    const uint32_t* wtl = wt + 32 * 516;
    const uint32_t* hbh = hb;
    const uint32_t* hbl = hb + 16 * 516;

    for (int t = 0; t < TT; t++) {
        // Prefetch pre for this thread's output.
        float pv = __ldg(pre + ((size_t)t * BB + eb) * HH + jbase + ejl);

        const __nv_bfloat16* hxh = g_hhh + (size_t)t * (BB * HH) + bBase * HH;
        const __nv_bfloat16* hxl = g_hhl + (size_t)t * (BB * HH) + bBase * HH;

        // Wait for this warp's 2 producers (all lanes acquire-poll).
        if (t > 0) {
            unsigned c0, c1;
            do {
                asm volatile("ld.acquire.gpu.global.u32 %0, [%1];"
                             : "=r"(c0) : "l"(f0) : "memory");
                asm volatile("ld.acquire.gpu.global.u32 %0, [%1];"
                             : "=r"(c1) : "l"(f1) : "memory");
            } while ((int)c0 < t || (int)c1 < t);
        }

        // Stage this warp's slice: 16 rows x 64 k x {hi,lo} = 4KB.
        {
            #pragma unroll
            for (int i = 0; i < 8; i++) {
                int L   = lane + i * 32;           // 0..255
                int mat = L >> 7;                  // 0 hi, 1 lo
                int rem = L & 127;
                int row = rem >> 3;                // 0..15
                int seg = rem & 7;                 // 16B segment of 128B
                const __nv_bfloat16* src =
                    (mat ? hxl : hxh) + row * HH + kq * 64 + seg * 8;
                uint32_t dst = hb_sm +
                    (((mat * 16 + row) * 516 + kq * 32 + seg * 4) << 2);
                asm volatile("cp.async.cg.shared.global [%0], [%1], 16;"
                             :: "r"(dst), "l"(src));
            }
            asm volatile("cp.async.commit_group;");
            asm volatile("cp.async.wait_group 0;");
            __syncwarp();
        }

        float d[4][4] = {};   // [nt][4 f32]

        #pragma unroll
        for (int s = 0; s < 4; s++) {
            const int w = kq * 32 + s * 8 + lc;

            uint32_t a0h = hbh[lg * 516 + w];
            uint32_t a1h = hbh[(lg + 8) * 516 + w];
            uint32_t a2h = hbh[lg * 516 + w + 4];
            uint32_t a3h = hbh[(lg + 8) * 516 + w + 4];
            uint32_t a0l = hbl[lg * 516 + w];
            uint32_t a1l = hbl[(lg + 8) * 516 + w];
            uint32_t a2l = hbl[lg * 516 + w + 4];
            uint32_t a3l = hbl[(lg + 8) * 516 + w + 4];

            #pragma unroll
            for (int nt = 0; nt < 4; nt++) {
                const int nr = nt * 8 + lg;
                uint32_t b0h = wth[nr * 516 + w];
                uint32_t b1h = wth[nr * 516 + w + 4];
                uint32_t b0l = wtl[nr * 516 + w];
                uint32_t b1l = wtl[nr * 516 + w + 4];
                mma16816(d[nt], a0h, a1h, a2h, a3h, b0h, b1h);
                mma16816(d[nt], a0h, a1h, a2h, a3h, b0l, b1l);
                mma16816(d[nt], a0l, a1l, a2l, a3l, b0h, b1h);
            }
        }

        // ---- two-phase k-reduce: warps 0-7 write, warps 8-15 accumulate ----
        if (kq < 8) {
            float* rp = red + kq * 576;           // 16*36
            #pragma unroll
            for (int nt = 0; nt < 4; nt++) {
                int col = nt * 8 + lc * 2;
                *(float2*)&rp[lg * 36 + col]       = make_float2(d[nt][0], d[nt][1]);
                *(float2*)&rp[(lg + 8) * 36 + col] = make_float2(d[nt][2], d[nt][3]);
            }
        }
        __syncthreads();
        if (kq >= 8) {
            float* rp = red + (kq - 8) * 576;
            #pragma unroll
            for (int nt = 0; nt < 4; nt++) {
                int col = nt * 8 + lc * 2;
                float2 p0 = *(float2*)&rp[lg * 36 + col];
                float2 p1 = *(float2*)&rp[(lg + 8) * 36 + col];
                *(float2*)&rp[lg * 36 + col] =
                    make_float2(p0.x + d[nt][0], p0.y + d[nt][1]);
                *(float2*)&rp[(lg + 8) * 36 + col] =
                    make_float2(p1.x + d[nt][2], p1.y + d[nt][3]);
            }
        }
        __syncthreads();

        // ---- epilogue: reduce 8 partials, +pre, tanh, publish exchange,
        //      release, then fp32 hid store (off the critical path).
        float v0;
        {
            float s0 = 0.f;
            #pragma unroll
            for (int q = 0; q < 8; q++)
                s0 += red[q * 576 + ebl * 36 + ejl];
            v0 = tanhf(pv + s0);

            __nv_bfloat16* nxh = g_hhh + (size_t)(t + 1) * (BB * HH);
            __nv_bfloat16* nxl = g_hhl + (size_t)(t + 1) * (BB * HH);
            __nv_bfloat16 h1 = __float2bfloat16(v0);
            __nv_bfloat16 l1 = __float2bfloat16(v0 - __bfloat162float(h1));
            nxh[(size_t)eb * HH + jbase + ejl] = h1;
            nxl[(size_t)eb * HH + jbase + ejl] = l1;
        }

        __threadfence();
        __syncthreads();
        if (tid == 0) {
            unsigned v = (unsigned)(t + 1);
            asm volatile("st.release.gpu.global.u32 [%0], %1;"
                         :: "l"(myFlag), "r"(v) : "memory");
        }

        // fp32 output store (consumers never read this; after release).
        hid[(size_t)t * (BB * HH) + (size_t)eb * HH + jbase + ejl] = v0;
    }
}

// ---------------------------------------------------------------------------
// Launch: splits -> HMMA pre-GEMM -> persistent HMMA recurrence -> HMMA
// out-GEMM (out-GEMM reads the recurrent kernel's bf16 h history directly).
// ---------------------------------------------------------------------------
extern "C" void kernel_launch(void* const* d_in, const int* in_sizes, int n_in,
                              void* d_out, int out_size)
{
    const float* x  = (const float*)d_in[0];
    const float* h0 = (const float*)d_in[1];
    const float* wI = (const float*)d_in[2];
    const float* wR = (const float*)d_in[3];
    const float* wO = (const float*)d_in[4];
    const float* bR = (const float*)d_in[5];
    const float* bO = (const float*)d_in[6];

    float* outp = (float*)d_out;            // [T,B,O]
    float* hid  = outp + OUT_ELEMS;         // [T,B,H]

    float* pre = nullptr;
    cudaGetSymbolAddress((void**)&pre, g_pre);
    __nv_bfloat16 *xh, *xl, *wih, *wil, *woh, *wol, *hhh, *hhl;
    cudaGetSymbolAddress((void**)&xh,  g_xh);
    cudaGetSymbolAddress((void**)&xl,  g_xl);
    cudaGetSymbolAddress((void**)&wih, g_wih);
    cudaGetSymbolAddress((void**)&wil, g_wil);
    cudaGetSymbolAddress((void**)&woh, g_woh);
    cudaGetSymbolAddress((void**)&wol, g_wol);
    cudaGetSymbolAddress((void**)&hhh, g_hhh);
    cudaGetSymbolAddress((void**)&hhl, g_hhl);

    cudaFuncSetAttribute(rnn_rec_mma,
                         cudaFuncAttributeMaxDynamicSharedMemorySize,
                         REC_SMEM_BYTES);
    cudaFuncSetAttribute(gemm_mma_split,
                         cudaFuncAttributeMaxDynamicSharedMemorySize,
                         GEMM_SMEM_BYTES);

    // fp32 -> bf16 hi/lo splits
    split_kernel<<<(TT * BB * II / 4 + 255) / 256, 256>>>(x, xh, xl, TT * BB * II / 4);
    split_kernel<<<(HH * II / 4 + 255) / 256, 256>>>(wI, wih, wil, HH * II / 4);
    split_kernel<<<(OO * HH / 4 + 255) / 256, 256>>>(wO, woh, wol, OO * HH / 4);

    // pre[T*B, H] = x @ wI^T + bR   (HMMA split)
    gemm_mma_split<<<dim3(TT * BB / 64, HH / 64), 256, GEMM_SMEM_BYTES>>>(
        xh, xl, wih, wil, bR, pre, TT * BB, HH, II);

    // recurrence (writes hid fp32 + bf16 hi/lo history)
    rnn_rec_mma<<<REC_CTAS, REC_THREADS, REC_SMEM_BYTES>>>(pre, h0, wR, hid);

    // outputs[T*B, O] = hid @ wO^T + bO  (HMMA split, A = bf16 history slot 1+)
    gemm_mma_split<<<dim3(TT * BB / 64, OO / 64), 256, GEMM_SMEM_BYTES>>>(
        hhh + BB * HH, hhl + BB * HH, woh, wol, bO, outp, TT * BB, OO, HH);
}